// round 15
// baseline (speedup 1.0000x reference)
#include <cuda_runtime.h>
#include <cuda_bf16.h>
#include <cuda_fp16.h>
#include <cstdint>

#define NMAX 65536
#define EMAX 800000
#define K1DIM 128   // 2H
#define C1 256      // 4H
#define C2 64       // H
#define H  64
#define EPSV 1e-5f

// ---- warp MMA helpers (plain sm_103-compatible: no tcgen05) -------------
__device__ __forceinline__ uint32_t smem_u32(const void* p) {
    uint32_t a;
    asm("{ .reg .u64 t; cvta.to.shared.u64 t, %1; cvt.u32.u64 %0, t; }"
        : "=r"(a) : "l"(p));
    return a;
}
__device__ __forceinline__ void ldsm_x4(uint32_t& r0, uint32_t& r1,
                                        uint32_t& r2, uint32_t& r3, uint32_t addr) {
    asm volatile("ldmatrix.sync.aligned.m8n8.x4.shared.b16 {%0,%1,%2,%3}, [%4];"
                 : "=r"(r0), "=r"(r1), "=r"(r2), "=r"(r3) : "r"(addr));
}
__device__ __forceinline__ void ldsm_x4_t(uint32_t& r0, uint32_t& r1,
                                          uint32_t& r2, uint32_t& r3, uint32_t addr) {
    asm volatile("ldmatrix.sync.aligned.m8n8.x4.trans.shared.b16 {%0,%1,%2,%3}, [%4];"
                 : "=r"(r0), "=r"(r1), "=r"(r2), "=r"(r3) : "r"(addr));
}
__device__ __forceinline__ void mma16816h(float* d,
                                          uint32_t a0, uint32_t a1, uint32_t a2, uint32_t a3,
                                          uint32_t b0, uint32_t b1) {
    asm volatile("mma.sync.aligned.m16n8k16.row.col.f32.f16.f16.f32 "
                 "{%0,%1,%2,%3}, {%4,%5,%6,%7}, {%8,%9}, {%0,%1,%2,%3};"
                 : "+f"(d[0]), "+f"(d[1]), "+f"(d[2]), "+f"(d[3])
                 : "r"(a0), "r"(a1), "r"(a2), "r"(a3), "r"(b0), "r"(b1));
}

// ================= scratch =================
__device__ float    g_Pt[(size_t)NMAX * C1];     // fp32 planes (gemm2)
__device__ float    g_Pb[(size_t)NMAX * C1];
__device__ uint32_t g_PtH[(size_t)NMAX * 128];   // bf16x2 planes (stats1)
__device__ uint32_t g_PbH[(size_t)NMAX * 128];
__device__ uint32_t g_Y2h[(size_t)EMAX * 32];    // fp16x2 layer-2 output
__device__ int      g_ci[EMAX];                  // decoded int32 col indices
__device__ int      g_ri[EMAX];                  // decoded int32 row indices
__device__ float    g_s1[2 * C1];
__device__ float    g_mr1[2 * C1];
__device__ float    g_s2[2 * C2];
__device__ float    g_mr2[2 * C2];
__device__ int      g_idx64;
__device__ int      g_cnt1;
__device__ int      g_cnt2;

// ================= pre: zero stats + decode indices to int32 =============
__global__ void k_pre(const int* __restrict__ ei_words, int E)
{
    __shared__ int sIs64;
    if (threadIdx.x == 0) {
        int orv = 0;
        #pragma unroll
        for (int i = 1; i < 32; i += 2) orv |= ei_words[i];
        sIs64 = (orv == 0) ? 1 : 0;
        if (blockIdx.x == 0) g_idx64 = sIs64;
    }
    __syncthreads();
    const int is64 = sIs64;
    const long long* e64 = (const long long*)ei_words;

    const int gid = blockIdx.x * blockDim.x + threadIdx.x;
    if (gid < 2 * C1) g_s1[gid] = 0.0f;
    if (gid < 2 * C2) g_s2[gid] = 0.0f;
    if (gid == 0) { g_cnt1 = 0; g_cnt2 = 0; }

    const int stride = gridDim.x * blockDim.x;
    for (int e = gid; e < E; e += stride) {
        g_ci[e] = is64 ? (int)e64[e]     : ei_words[e];
        g_ri[e] = is64 ? (int)e64[E + e] : ei_words[E + e];
    }
}

// ================= node projection (fp32 SIMT, fp32+bf16 outputs) ========
__global__ __launch_bounds__(256, 1)
void k_proj(const float* __restrict__ emb,
            const float* __restrict__ W1,
            const float* __restrict__ b1,
            int N)
{
    extern __shared__ float sm[];
    float* Ws = sm;                 // 128*256
    float* As = sm + K1DIM * C1;    // 32*64

    const int tid = threadIdx.x;
    for (int i = tid; i < K1DIM * C1 / 4; i += blockDim.x)
        ((float4*)Ws)[i] = ((const float4*)W1)[i];

    const int tx = tid & 31;
    const int ty = tid >> 5;

    float biasReg[8];
    #pragma unroll
    for (int c = 0; c < 8; c++) biasReg[c] = b1[tx * 8 + c];

    __syncthreads();

    const int nTiles = (N + 31) / 32;
    for (int tile = blockIdx.x; tile < nTiles; tile += gridDim.x) {
        const int base = tile * 32;
        for (int i = tid; i < 32 * 16; i += blockDim.x) {
            const int r = i >> 4, q = i & 15;
            const int n = base + r;
            float4 v = make_float4(0.f, 0.f, 0.f, 0.f);
            if (n < N) v = ((const float4*)(emb + (size_t)n * H))[q];
            ((float4*)(As + r * H))[q] = v;
        }
        __syncthreads();

        const float* Arow = As + (ty * 4) * H;

        #define PROJ_PASS(ROWOFF, DST, DSTH, ADDBIAS)                         \
        {                                                                     \
            float acc[4][8];                                                  \
            _Pragma("unroll")                                                 \
            for (int r = 0; r < 4; r++)                                       \
                _Pragma("unroll")                                             \
                for (int c = 0; c < 8; c++) acc[r][c] = 0.0f;                 \
            _Pragma("unroll 4")                                               \
            for (int k = 0; k < H; k++) {                                     \
                const float4 w0 = *((const float4*)(Ws + (ROWOFF + k) * C1 + tx * 8));     \
                const float4 w1 = *((const float4*)(Ws + (ROWOFF + k) * C1 + tx * 8 + 4)); \
                const float a0 = Arow[k];                                     \
                const float a1 = Arow[H + k];                                 \
                const float a2 = Arow[2 * H + k];                             \
                const float a3 = Arow[3 * H + k];                             \
                _Pragma("unroll")                                             \
                for (int r = 0; r < 4; r++) {                                 \
                    const float a = (r == 0) ? a0 : (r == 1) ? a1 : (r == 2) ? a2 : a3; \
                    acc[r][0] += a * w0.x; acc[r][1] += a * w0.y;             \
                    acc[r][2] += a * w0.z; acc[r][3] += a * w0.w;             \
                    acc[r][4] += a * w1.x; acc[r][5] += a * w1.y;             \
                    acc[r][6] += a * w1.z; acc[r][7] += a * w1.w;             \
                }                                                             \
            }                                                                 \
            _Pragma("unroll")                                                 \
            for (int r = 0; r < 4; r++) {                                     \
                const int n = base + ty * 4 + r;                              \
                if (n < N) {                                                  \
                    float v[8];                                               \
                    _Pragma("unroll")                                         \
                    for (int c = 0; c < 8; c++)                               \
                        v[c] = acc[r][c] + (ADDBIAS ? biasReg[c] : 0.0f);     \
                    float4* dst = (float4*)(DST + (size_t)n * C1 + tx * 8);   \
                    dst[0] = make_float4(v[0], v[1], v[2], v[3]);             \
                    dst[1] = make_float4(v[4], v[5], v[6], v[7]);             \
                    const __nv_bfloat162 p01 = __floats2bfloat162_rn(v[0], v[1]); \
                    const __nv_bfloat162 p23 = __floats2bfloat162_rn(v[2], v[3]); \
                    const __nv_bfloat162 p45 = __floats2bfloat162_rn(v[4], v[5]); \
                    const __nv_bfloat162 p67 = __floats2bfloat162_rn(v[6], v[7]); \
                    uint4 u;                                                  \
                    u.x = *(const uint32_t*)&p01; u.y = *(const uint32_t*)&p23; \
                    u.z = *(const uint32_t*)&p45; u.w = *(const uint32_t*)&p67; \
                    ((uint4*)(DSTH + (size_t)n * 128))[tx] = u;               \
                }                                                             \
            }                                                                 \
        }
        PROJ_PASS(0,  g_Pt, g_PtH, 1)
        PROJ_PASS(64, g_Pb, g_PbH, 0)
        #undef PROJ_PASS
        __syncthreads();
    }
}

// ========== layer-1 stats: full-population gather + fused fin1 ===========
__global__ __launch_bounds__(256)
void k_stats1(int E)
{
    const int c2   = threadIdx.x & 127;
    const int half = threadIdx.x >> 7;

    float s0 = 0.f, q0 = 0.f, s1 = 0.f, q1 = 0.f;
    const int stride = gridDim.x * 8;
    for (int e0 = blockIdx.x * 8 + half * 4; e0 < E; e0 += stride) {
        uint32_t ta[4], tb[4];
        int nv = 0;
        #pragma unroll
        for (int j = 0; j < 4; j++) {
            const int e = e0 + j;
            if (e < E) {
                const int ci = __ldg(&g_ci[e]);
                const int ri = __ldg(&g_ri[e]);
                ta[j] = __ldg(g_PtH + (size_t)ci * 128 + c2);
                tb[j] = __ldg(g_PbH + (size_t)ri * 128 + c2);
                nv = j + 1;
            }
        }
        #pragma unroll
        for (int j = 0; j < 4; j++) {
            if (j < nv) {
                const float2 af = __bfloat1622float2(*(const __nv_bfloat162*)&ta[j]);
                const float2 bf = __bfloat1622float2(*(const __nv_bfloat162*)&tb[j]);
                const float v0 = af.x + bf.x;
                const float v1 = af.y + bf.y;
                s0 += v0; q0 += v0 * v0;
                s1 += v1; q1 += v1 * v1;
            }
        }
    }
    atomicAdd(&g_s1[2 * c2],          s0);
    atomicAdd(&g_s1[2 * c2 + 1],      s1);
    atomicAdd(&g_s1[C1 + 2 * c2],     q0);
    atomicAdd(&g_s1[C1 + 2 * c2 + 1], q1);

    // ---- fused fin1: last block computes mean/rstd ----
    __shared__ int sLast;
    __threadfence();
    __syncthreads();
    if (threadIdx.x == 0)
        sLast = (atomicAdd(&g_cnt1, 1) == (int)gridDim.x - 1) ? 1 : 0;
    __syncthreads();
    if (sLast) {
        const int c = threadIdx.x;   // 256 channels
        const float inv = 1.0f / (float)E;
        const float m   = __ldcg(&g_s1[c]) * inv;
        const float var = __ldcg(&g_s1[C1 + c]) * inv - m * m;
        g_mr1[c]      = m;
        g_mr1[C1 + c] = rsqrtf(var + EPSV);
    }
}

// ================= layer 2: pipelined single-plane fp16 MMA ==============
// 256 threads = 8 warps per CTA, 2 CTAs/SM (cross-CTA latency hiding).
// Tile = 64 edges x 64 cols, K = 256, double-buffered fp16 A plane,
// single fp16 B plane (W2^T). Warp: wm = wid&3 -> rows [wm*16,+16);
// wn = wid>>2 -> cols [wn*32,+32). fp32 gather; int32 indices.
#define TR 64
#define ASTR 264               // A smem row stride (fp16), 8-elem pad
#define BSTR 72                // B smem row stride (fp16), 8-elem pad
#define ABUF (TR * ASTR * 2)   // 33792 B per buffer
#define BPLANE (C1 * BSTR * 2) // 36864 B
#define OFF_B (2 * ABUF)       // 67584
#define SMT_G2 (OFF_B + BPLANE)   // 104448 -> 2 CTAs/SM

__device__ __forceinline__ void cvt4h(float4 a, float4 b, float4 ms, float4 rs,
                                      uint32_t& h01, uint32_t& h23)
{
    const float v0 = fmaxf(0.f, (a.x + b.x - ms.x) * rs.x);
    const float v1 = fmaxf(0.f, (a.y + b.y - ms.y) * rs.y);
    const float v2 = fmaxf(0.f, (a.z + b.z - ms.z) * rs.z);
    const float v3 = fmaxf(0.f, (a.w + b.w - ms.w) * rs.w);
    const __half2 H01 = __floats2half2_rn(v0, v1);
    const __half2 H23 = __floats2half2_rn(v2, v3);
    h01 = *(const uint32_t*)&H01; h23 = *(const uint32_t*)&H23;
}

__global__ __launch_bounds__(256, 2)
void k_gemm2_mma(const float* __restrict__ W2,
                 const float* __restrict__ b2,
                 int E)
{
    extern __shared__ char smraw[];
    const uint32_t smBase = smem_u32(smraw);
    __half* Bh = (__half*)(smraw + OFF_B);
    const uint32_t BhA = smBase + OFF_B;

    const int tid  = threadIdx.x;
    const int lane = tid & 31;
    const int wid  = tid >> 5;

    // --- build W2^T fp16 plane ---
    for (int i = tid; i < C1 * C2; i += 256) {
        const int k = i >> 6, n = i & 63;
        Bh[k * BSTR + n] = __float2half(W2[k * C2 + n]);
    }

    // loop-invariant per-thread normalization params (q = tid&63 fixed)
    const int q  = tid & 63;
    const int rq = tid >> 6;                 // base row 0..3; rows rq + j*4
    const float4 ms4 = ((const float4*)g_mr1)[q];
    const float4 rs4 = ((const float4*)(g_mr1 + C1))[q];

    const int wm = wid & 3;          // row group (16 rows)
    const int wn = wid >> 2;         // col group (32 cols)
    const int tg = lane & 3;
    const uint32_t aOff = (uint32_t)((wm * 16 + (lane & 15)) * ASTR + (lane >> 4) * 8) * 2;
    const uint32_t bOff = (uint32_t)(((lane & 7) + ((lane >> 3) & 1) * 8) * BSTR
                                     + wn * 32 + (lane >> 4) * 8) * 2;

    float bias[8];
    #pragma unroll
    for (int nb = 0; nb < 4; nb++) {
        bias[nb * 2 + 0] = b2[wn * 32 + nb * 8 + tg * 2];
        bias[nb * 2 + 1] = b2[wn * 32 + nb * 8 + tg * 2 + 1];
    }

    float sSum[8], sSq[8];
    #pragma unroll
    for (int i = 0; i < 8; i++) { sSum[i] = 0.f; sSq[i] = 0.f; }

    const int nTiles = (E + TR - 1) / TR;
    const int stride = gridDim.x;

    auto gatherRow = [&](int e, float4& a, float4& b) {
        a = make_float4(0.f, 0.f, 0.f, 0.f);
        b = make_float4(0.f, 0.f, 0.f, 0.f);
        if (e < E) {
            const int ci = __ldg(&g_ci[e]);
            const int ri = __ldg(&g_ri[e]);
            a = ((const float4*)(g_Pt + (size_t)ci * C1))[q];
            b = ((const float4*)(g_Pb + (size_t)ri * C1))[q];
        }
    };
    auto stsRow = [&](char* bA, int r, uint32_t h01, uint32_t h23) {
        uint32_t* ah = (uint32_t*)(bA + r * (ASTR * 2));
        ah[q * 2] = h01; ah[q * 2 + 1] = h23;
    };

    // prologue: full build of first tile into buffer 0 (16 rows/thread)
    if (blockIdx.x < nTiles) {
        #pragma unroll
        for (int j = 0; j < 16; j++) {
            const int r = rq + j * 4;
            float4 a, b;
            gatherRow(blockIdx.x * TR + r, a, b);
            uint32_t h01, h23;
            cvt4h(a, b, ms4, rs4, h01, h23);
            stsRow(smraw, r, h01, h23);
        }
    }
    __syncthreads();

    int cur = 0;
    for (int t = blockIdx.x; t < nTiles; t += stride) {
        const int nt = t + stride;
        const bool pf = (nt < nTiles);
        const uint32_t curA = smBase + cur * ABUF;
        char* nxtA = smraw + (cur ^ 1) * ABUF;

        float acc[4][4];
        #pragma unroll
        for (int nb = 0; nb < 4; nb++)
            #pragma unroll
            for (int c = 0; c < 4; c++) acc[nb][c] = 0.0f;

        #define MMA_STEP(kb)                                                  \
        {                                                                     \
            uint32_t a0, a1, a2, a3, b0, b1, b2_, b3_, c0, c1, c2_, c3_;      \
            ldsm_x4(a0, a1, a2, a3, curA + aOff + (kb) * 32);                 \
            const uint32_t bk = BhA + bOff + (kb) * (16 * BSTR * 2);          \
            ldsm_x4_t(b0, b1, b2_, b3_, bk);                                  \
            ldsm_x4_t(c0, c1, c2_, c3_, bk + 32);                             \
            mma16816h(acc[0], a0, a1, a2, a3, b0, b1);                        \
            mma16816h(acc[1], a0, a1, a2, a3, b2_, b3_);                      \
            mma16816h(acc[2], a0, a1, a2, a3, c0, c1);                        \
            mma16816h(acc[3], a0, a1, a2, a3, c2_, c3_);                      \
        }

        float4 pa[4], pb[4];
        #define GATHER_G(g)                                                   \
            _Pragma("unroll")                                                 \
            for (int k = 0; k < 4; k++)                                       \
                gatherRow(nt * TR + rq + ((g) * 4 + k) * 4, pa[k], pb[k]);
        #define STS_G(g)                                                      \
            _Pragma("unroll")                                                 \
            for (int k = 0; k < 4; k++) {                                     \
                uint32_t h01, h23;                                            \
                cvt4h(pa[k], pb[k], ms4, rs4, h01, h23);                      \
                stsRow(nxtA, rq + ((g) * 4 + k) * 4, h01, h23);               \
            }

        if (pf) { GATHER_G(0) }
        MMA_STEP(0) MMA_STEP(1) MMA_STEP(2) MMA_STEP(3)
        if (pf) { STS_G(0) GATHER_G(1) }
        MMA_STEP(4) MMA_STEP(5) MMA_STEP(6) MMA_STEP(7)
        if (pf) { STS_G(1) GATHER_G(2) }
        MMA_STEP(8) MMA_STEP(9) MMA_STEP(10) MMA_STEP(11)
        if (pf) { STS_G(2) GATHER_G(3) }
        MMA_STEP(12) MMA_STEP(13) MMA_STEP(14) MMA_STEP(15)
        if (pf) { STS_G(3) }

        #undef MMA_STEP
        #undef GATHER_G
        #undef STS_G

        // ---- epilogue: +bias, store Y2 (fp16x2), accumulate stats2 ----
        {
            const int g_  = lane >> 2;
            const int e0 = t * TR + wm * 16 + g_;
            const int e1 = e0 + 8;
            #pragma unroll
            for (int nb = 0; nb < 4; nb++) {
                const int c = wn * 32 + nb * 8 + tg * 2;
                const float bx = bias[nb * 2], by = bias[nb * 2 + 1];
                if (e0 < E) {
                    const float ox = acc[nb][0] + bx;
                    const float oy = acc[nb][1] + by;
                    const __half2 h = __floats2half2_rn(ox, oy);
                    g_Y2h[(size_t)e0 * 32 + (c >> 1)] = *(const uint32_t*)&h;
                    sSum[nb * 2 + 0] += ox; sSq[nb * 2 + 0] += ox * ox;
                    sSum[nb * 2 + 1] += oy; sSq[nb * 2 + 1] += oy * oy;
                }
                if (e1 < E) {
                    const float ox = acc[nb][2] + bx;
                    const float oy = acc[nb][3] + by;
                    const __half2 h = __floats2half2_rn(ox, oy);
                    g_Y2h[(size_t)e1 * 32 + (c >> 1)] = *(const uint32_t*)&h;
                    sSum[nb * 2 + 0] += ox; sSq[nb * 2 + 0] += ox * ox;
                    sSum[nb * 2 + 1] += oy; sSq[nb * 2 + 1] += oy * oy;
                }
            }
        }
        __syncthreads();
        cur ^= 1;
    }

    // ---- stats2 reduction: smem scratch, global atomics, fused fin2 ----
    float* sS = (float*)smraw;       // 64 floats
    float* sQ = sS + 64;             // 64 floats
    __syncthreads();
    if (tid < 128) sS[tid] = 0.f;
    __syncthreads();
    #pragma unroll
    for (int nb = 0; nb < 4; nb++) {
        const int c = wn * 32 + nb * 8 + tg * 2;
        atomicAdd(&sS[c],     sSum[nb * 2 + 0]);
        atomicAdd(&sS[c + 1], sSum[nb * 2 + 1]);
        atomicAdd(&sQ[c],     sSq[nb * 2 + 0]);
        atomicAdd(&sQ[c + 1], sSq[nb * 2 + 1]);
    }
    __syncthreads();
    if (tid < C2) {
        atomicAdd(&g_s2[tid],      sS[tid]);
        atomicAdd(&g_s2[C2 + tid], sQ[tid]);
    }

    __shared__ int sLast;
    __threadfence();
    __syncthreads();
    if (tid == 0)
        sLast = (atomicAdd(&g_cnt2, 1) == (int)gridDim.x - 1) ? 1 : 0;
    __syncthreads();
    if (sLast && tid < C2) {
        const float inv = 1.0f / (float)E;
        const float m   = __ldcg(&g_s2[tid]) * inv;
        const float var = __ldcg(&g_s2[C2 + tid]) * inv - m * m;
        g_mr2[tid]      = m;
        g_mr2[C2 + tid] = rsqrtf(var + EPSV);
    }
}

// ================= layer 3: 2 edges/warp, fp16 Y2 reads =================
__global__ __launch_bounds__(256)
void k_out(const float* __restrict__ W3,
           const float* __restrict__ b3,
           float* __restrict__ out,
           int E)
{
    __shared__ float w[C2], m[C2], rs[C2];
    const int tid = threadIdx.x;
    if (tid < C2) {
        w[tid]  = W3[tid];
        m[tid]  = g_mr2[tid];
        rs[tid] = g_mr2[C2 + tid];
    }
    __syncthreads();

    const int lane = tid & 31;
    const int warp = tid >> 5;
    const int sub  = lane >> 4;           // 0/1: which edge in warp
    const int cq   = lane & 15;           // 4 channels each
    const int e = blockIdx.x * 16 + warp * 2 + sub;
    const bool valid = (e < E);

    float p = 0.0f;
    if (valid) {
        const uint2 u = ((const uint2*)(g_Y2h + (size_t)e * 32))[cq];
        const float2 y01 = __half22float2(*(const __half2*)&u.x);
        const float2 y23 = __half22float2(*(const __half2*)&u.y);
        const int c = cq * 4;
        p  = fmaxf(0.f, (y01.x - m[c])     * rs[c])     * w[c];
        p += fmaxf(0.f, (y01.y - m[c + 1]) * rs[c + 1]) * w[c + 1];
        p += fmaxf(0.f, (y23.x - m[c + 2]) * rs[c + 2]) * w[c + 2];
        p += fmaxf(0.f, (y23.y - m[c + 3]) * rs[c + 3]) * w[c + 3];
    }
    #pragma unroll
    for (int o = 8; o > 0; o >>= 1) p += __shfl_xor_sync(0xffffffffu, p, o);
    if (valid && cq == 0) out[e] = p + b3[0];
}

// ================= launch =================
extern "C" void kernel_launch(void* const* d_in, const int* in_sizes, int n_in,
                              void* d_out, int out_size)
{
    const float* emb = (const float*)d_in[0];
    const void*  ei  = d_in[1];
    const float* W1  = (const float*)d_in[2];
    const float* b1  = (const float*)d_in[3];
    const float* W2  = (const float*)d_in[4];
    const float* b2  = (const float*)d_in[5];
    const float* W3  = (const float*)d_in[6];
    const float* b3  = (const float*)d_in[7];
    float* out = (float*)d_out;

    const int N = in_sizes[0] / H;
    const int E = in_sizes[1] / 2;

    int dev = 0;
    cudaGetDevice(&dev);
    int nsm = 148;
    cudaDeviceGetAttribute(&nsm, cudaDevAttrMultiProcessorCount, dev);

    const int smP = (K1DIM * C1 + 32 * H) * (int)sizeof(float);   // 139264
    cudaFuncSetAttribute(k_proj,      cudaFuncAttributeMaxDynamicSharedMemorySize, smP);
    cudaFuncSetAttribute(k_gemm2_mma, cudaFuncAttributeMaxDynamicSharedMemorySize, SMT_G2);

    const int nTiles = (E + TR - 1) / TR;
    int g2 = 2 * nsm;
    if (g2 > nTiles) g2 = nTiles;

    k_pre<<<1024, 256>>>((const int*)ei, E);
    k_proj<<<nsm, 256, smP>>>(emb, W1, b1, N);
    k_stats1<<<nsm * 8, 256>>>(E);
    k_gemm2_mma<<<g2, 256, SMT_G2>>>(W2, b2, E);
    k_out<<<(E + 15) / 16, 256>>>(W3, b3, out, E);
}

// round 16
// speedup vs baseline: 1.0065x; 1.0065x over previous
#include <cuda_runtime.h>
#include <cuda_bf16.h>
#include <cuda_fp16.h>
#include <cstdint>

#define NMAX 65536
#define EMAX 800000
#define K1DIM 128   // 2H
#define C1 256      // 4H
#define C2 64       // H
#define H  64
#define EPSV 1e-5f

// ---- warp MMA helpers (plain sm_103-compatible: no tcgen05) -------------
__device__ __forceinline__ uint32_t smem_u32(const void* p) {
    uint32_t a;
    asm("{ .reg .u64 t; cvta.to.shared.u64 t, %1; cvt.u32.u64 %0, t; }"
        : "=r"(a) : "l"(p));
    return a;
}
__device__ __forceinline__ void ldsm_x4(uint32_t& r0, uint32_t& r1,
                                        uint32_t& r2, uint32_t& r3, uint32_t addr) {
    asm volatile("ldmatrix.sync.aligned.m8n8.x4.shared.b16 {%0,%1,%2,%3}, [%4];"
                 : "=r"(r0), "=r"(r1), "=r"(r2), "=r"(r3) : "r"(addr));
}
__device__ __forceinline__ void ldsm_x4_t(uint32_t& r0, uint32_t& r1,
                                          uint32_t& r2, uint32_t& r3, uint32_t addr) {
    asm volatile("ldmatrix.sync.aligned.m8n8.x4.trans.shared.b16 {%0,%1,%2,%3}, [%4];"
                 : "=r"(r0), "=r"(r1), "=r"(r2), "=r"(r3) : "r"(addr));
}
__device__ __forceinline__ void mma16816h(float* d,
                                          uint32_t a0, uint32_t a1, uint32_t a2, uint32_t a3,
                                          uint32_t b0, uint32_t b1) {
    asm volatile("mma.sync.aligned.m16n8k16.row.col.f32.f16.f16.f32 "
                 "{%0,%1,%2,%3}, {%4,%5,%6,%7}, {%8,%9}, {%0,%1,%2,%3};"
                 : "+f"(d[0]), "+f"(d[1]), "+f"(d[2]), "+f"(d[3])
                 : "r"(a0), "r"(a1), "r"(a2), "r"(a3), "r"(b0), "r"(b1));
}

// ================= scratch =================
__device__ float    g_Pt[(size_t)NMAX * C1];     // fp32 planes (gemm2)
__device__ float    g_Pb[(size_t)NMAX * C1];
__device__ uint32_t g_PtH[(size_t)NMAX * 128];   // bf16x2 planes (stats1)
__device__ uint32_t g_PbH[(size_t)NMAX * 128];
__device__ uint32_t g_Y2h[(size_t)EMAX * 32];    // fp16x2 layer-2 output
__device__ int      g_ci[EMAX];                  // decoded int32 col indices
__device__ int      g_ri[EMAX];                  // decoded int32 row indices
__device__ float    g_s1[2 * C1];
__device__ float    g_mr1[2 * C1];
__device__ float    g_s2[2 * C2];
__device__ float    g_mr2[2 * C2];
__device__ int      g_idx64;
__device__ int      g_cnt1;
__device__ int      g_cnt2;

// ================= pre: zero stats + decode indices to int32 =============
__global__ void k_pre(const int* __restrict__ ei_words, int E)
{
    __shared__ int sIs64;
    if (threadIdx.x == 0) {
        int orv = 0;
        #pragma unroll
        for (int i = 1; i < 32; i += 2) orv |= ei_words[i];
        sIs64 = (orv == 0) ? 1 : 0;
        if (blockIdx.x == 0) g_idx64 = sIs64;
    }
    __syncthreads();
    const int is64 = sIs64;
    const long long* e64 = (const long long*)ei_words;

    const int gid = blockIdx.x * blockDim.x + threadIdx.x;
    if (gid < 2 * C1) g_s1[gid] = 0.0f;
    if (gid < 2 * C2) g_s2[gid] = 0.0f;
    if (gid == 0) { g_cnt1 = 0; g_cnt2 = 0; }

    const int stride = gridDim.x * blockDim.x;
    for (int e = gid; e < E; e += stride) {
        g_ci[e] = is64 ? (int)e64[e]     : ei_words[e];
        g_ri[e] = is64 ? (int)e64[E + e] : ei_words[E + e];
    }
}

// ================= node projection (fp32 SIMT, fp32+bf16 outputs) ========
__global__ __launch_bounds__(256, 1)
void k_proj(const float* __restrict__ emb,
            const float* __restrict__ W1,
            const float* __restrict__ b1,
            int N)
{
    extern __shared__ float sm[];
    float* Ws = sm;                 // 128*256
    float* As = sm + K1DIM * C1;    // 32*64

    const int tid = threadIdx.x;
    for (int i = tid; i < K1DIM * C1 / 4; i += blockDim.x)
        ((float4*)Ws)[i] = ((const float4*)W1)[i];

    const int tx = tid & 31;
    const int ty = tid >> 5;

    float biasReg[8];
    #pragma unroll
    for (int c = 0; c < 8; c++) biasReg[c] = b1[tx * 8 + c];

    __syncthreads();

    const int nTiles = (N + 31) / 32;
    for (int tile = blockIdx.x; tile < nTiles; tile += gridDim.x) {
        const int base = tile * 32;
        for (int i = tid; i < 32 * 16; i += blockDim.x) {
            const int r = i >> 4, q = i & 15;
            const int n = base + r;
            float4 v = make_float4(0.f, 0.f, 0.f, 0.f);
            if (n < N) v = ((const float4*)(emb + (size_t)n * H))[q];
            ((float4*)(As + r * H))[q] = v;
        }
        __syncthreads();

        const float* Arow = As + (ty * 4) * H;

        #define PROJ_PASS(ROWOFF, DST, DSTH, ADDBIAS)                         \
        {                                                                     \
            float acc[4][8];                                                  \
            _Pragma("unroll")                                                 \
            for (int r = 0; r < 4; r++)                                       \
                _Pragma("unroll")                                             \
                for (int c = 0; c < 8; c++) acc[r][c] = 0.0f;                 \
            _Pragma("unroll 4")                                               \
            for (int k = 0; k < H; k++) {                                     \
                const float4 w0 = *((const float4*)(Ws + (ROWOFF + k) * C1 + tx * 8));     \
                const float4 w1 = *((const float4*)(Ws + (ROWOFF + k) * C1 + tx * 8 + 4)); \
                const float a0 = Arow[k];                                     \
                const float a1 = Arow[H + k];                                 \
                const float a2 = Arow[2 * H + k];                             \
                const float a3 = Arow[3 * H + k];                             \
                _Pragma("unroll")                                             \
                for (int r = 0; r < 4; r++) {                                 \
                    const float a = (r == 0) ? a0 : (r == 1) ? a1 : (r == 2) ? a2 : a3; \
                    acc[r][0] += a * w0.x; acc[r][1] += a * w0.y;             \
                    acc[r][2] += a * w0.z; acc[r][3] += a * w0.w;             \
                    acc[r][4] += a * w1.x; acc[r][5] += a * w1.y;             \
                    acc[r][6] += a * w1.z; acc[r][7] += a * w1.w;             \
                }                                                             \
            }                                                                 \
            _Pragma("unroll")                                                 \
            for (int r = 0; r < 4; r++) {                                     \
                const int n = base + ty * 4 + r;                              \
                if (n < N) {                                                  \
                    float v[8];                                               \
                    _Pragma("unroll")                                         \
                    for (int c = 0; c < 8; c++)                               \
                        v[c] = acc[r][c] + (ADDBIAS ? biasReg[c] : 0.0f);     \
                    float4* dst = (float4*)(DST + (size_t)n * C1 + tx * 8);   \
                    dst[0] = make_float4(v[0], v[1], v[2], v[3]);             \
                    dst[1] = make_float4(v[4], v[5], v[6], v[7]);             \
                    const __nv_bfloat162 p01 = __floats2bfloat162_rn(v[0], v[1]); \
                    const __nv_bfloat162 p23 = __floats2bfloat162_rn(v[2], v[3]); \
                    const __nv_bfloat162 p45 = __floats2bfloat162_rn(v[4], v[5]); \
                    const __nv_bfloat162 p67 = __floats2bfloat162_rn(v[6], v[7]); \
                    uint4 u;                                                  \
                    u.x = *(const uint32_t*)&p01; u.y = *(const uint32_t*)&p23; \
                    u.z = *(const uint32_t*)&p45; u.w = *(const uint32_t*)&p67; \
                    ((uint4*)(DSTH + (size_t)n * 128))[tx] = u;               \
                }                                                             \
            }                                                                 \
        }
        PROJ_PASS(0,  g_Pt, g_PtH, 1)
        PROJ_PASS(64, g_Pb, g_PbH, 0)
        #undef PROJ_PASS
        __syncthreads();
    }
}

// ========== layer-1 stats: full-population gather + fused fin1 ===========
__global__ __launch_bounds__(256)
void k_stats1(int E)
{
    const int c2   = threadIdx.x & 127;
    const int half = threadIdx.x >> 7;

    float s0 = 0.f, q0 = 0.f, s1 = 0.f, q1 = 0.f;
    const int stride = gridDim.x * 8;
    for (int e0 = blockIdx.x * 8 + half * 4; e0 < E; e0 += stride) {
        uint32_t ta[4], tb[4];
        int nv = 0;
        #pragma unroll
        for (int j = 0; j < 4; j++) {
            const int e = e0 + j;
            if (e < E) {
                const int ci = __ldg(&g_ci[e]);
                const int ri = __ldg(&g_ri[e]);
                ta[j] = __ldg(g_PtH + (size_t)ci * 128 + c2);
                tb[j] = __ldg(g_PbH + (size_t)ri * 128 + c2);
                nv = j + 1;
            }
        }
        #pragma unroll
        for (int j = 0; j < 4; j++) {
            if (j < nv) {
                const float2 af = __bfloat1622float2(*(const __nv_bfloat162*)&ta[j]);
                const float2 bf = __bfloat1622float2(*(const __nv_bfloat162*)&tb[j]);
                const float v0 = af.x + bf.x;
                const float v1 = af.y + bf.y;
                s0 += v0; q0 += v0 * v0;
                s1 += v1; q1 += v1 * v1;
            }
        }
    }
    atomicAdd(&g_s1[2 * c2],          s0);
    atomicAdd(&g_s1[2 * c2 + 1],      s1);
    atomicAdd(&g_s1[C1 + 2 * c2],     q0);
    atomicAdd(&g_s1[C1 + 2 * c2 + 1], q1);

    // ---- fused fin1: last block computes mean/rstd ----
    __shared__ int sLast;
    __threadfence();
    __syncthreads();
    if (threadIdx.x == 0)
        sLast = (atomicAdd(&g_cnt1, 1) == (int)gridDim.x - 1) ? 1 : 0;
    __syncthreads();
    if (sLast) {
        const int c = threadIdx.x;   // 256 channels
        const float inv = 1.0f / (float)E;
        const float m   = __ldcg(&g_s1[c]) * inv;
        const float var = __ldcg(&g_s1[C1 + c]) * inv - m * m;
        g_mr1[c]      = m;
        g_mr1[C1 + c] = rsqrtf(var + EPSV);
    }
}

// ================= layer 2: pipelined single-plane fp16 MMA ==============
// 512 threads = 16 warps, 1 CTA/SM. Tile = 128 edges x 64 cols, K = 256,
// double-buffered fp16 A plane, single fp16 B plane (W2^T).
// Inner loop: fragment double-buffering (ldsm for kb+1 issued during kb's
// MMAs); gather prefetch in 8 groups of 2 rows interleaved every 2 k-steps.
#define TR 128
#define ASTR 264               // A smem row stride (fp16), 8-elem pad
#define BSTR 72                // B smem row stride (fp16), 8-elem pad
#define ABUF (TR * ASTR * 2)   // 67584 B per buffer
#define BPLANE (C1 * BSTR * 2) // 36864 B
#define OFF_B (2 * ABUF)       // 135168
#define SMT_G2 (OFF_B + BPLANE + 256)   // + bias stash

__device__ __forceinline__ void cvt4h(float4 a, float4 b, float4 ms, float4 rs,
                                      uint32_t& h01, uint32_t& h23)
{
    const float v0 = fmaxf(0.f, (a.x + b.x - ms.x) * rs.x);
    const float v1 = fmaxf(0.f, (a.y + b.y - ms.y) * rs.y);
    const float v2 = fmaxf(0.f, (a.z + b.z - ms.z) * rs.z);
    const float v3 = fmaxf(0.f, (a.w + b.w - ms.w) * rs.w);
    const __half2 H01 = __floats2half2_rn(v0, v1);
    const __half2 H23 = __floats2half2_rn(v2, v3);
    h01 = *(const uint32_t*)&H01; h23 = *(const uint32_t*)&H23;
}

__global__ __launch_bounds__(512, 1)
void k_gemm2_mma(const float* __restrict__ W2,
                 const float* __restrict__ b2,
                 int E)
{
    extern __shared__ char smraw[];
    const uint32_t smBase = smem_u32(smraw);
    __half* Bh = (__half*)(smraw + OFF_B);
    const uint32_t BhA = smBase + OFF_B;
    float* b2s = (float*)(smraw + OFF_B + BPLANE);

    const int tid  = threadIdx.x;
    const int lane = tid & 31;
    const int wid  = tid >> 5;

    // --- build W2^T fp16 plane + bias stash ---
    for (int i = tid; i < C1 * C2; i += 512) {
        const int k = i >> 6, n = i & 63;
        Bh[k * BSTR + n] = __float2half(W2[k * C2 + n]);
    }
    if (tid < C2) b2s[tid] = b2[tid];

    // loop-invariant per-thread normalization params (q = tid&63 fixed)
    const int q  = tid & 63;
    const int rq = tid >> 6;                 // base row 0..7; rows rq + j*8
    const float4 ms4 = ((const float4*)g_mr1)[q];
    const float4 rs4 = ((const float4*)(g_mr1 + C1))[q];

    const int wm = wid & 7;          // row group (16 rows)
    const int wn = wid >> 3;         // col group (32 cols)
    const int tg = lane & 3;
    const uint32_t aOff = (uint32_t)((wm * 16 + (lane & 15)) * ASTR + (lane >> 4) * 8) * 2;
    const uint32_t bOff = (uint32_t)(((lane & 7) + ((lane >> 3) & 1) * 8) * BSTR
                                     + wn * 32 + (lane >> 4) * 8) * 2;

    float sSum[8], sSq[8];
    #pragma unroll
    for (int i = 0; i < 8; i++) { sSum[i] = 0.f; sSq[i] = 0.f; }

    const int nTiles = (E + TR - 1) / TR;
    const int stride = gridDim.x;

    auto gatherRow = [&](int e, float4& a, float4& b) {
        a = make_float4(0.f, 0.f, 0.f, 0.f);
        b = make_float4(0.f, 0.f, 0.f, 0.f);
        if (e < E) {
            const int ci = __ldg(&g_ci[e]);
            const int ri = __ldg(&g_ri[e]);
            a = ((const float4*)(g_Pt + (size_t)ci * C1))[q];
            b = ((const float4*)(g_Pb + (size_t)ri * C1))[q];
        }
    };
    auto stsRow = [&](char* bA, int r, uint32_t h01, uint32_t h23) {
        uint32_t* ah = (uint32_t*)(bA + r * (ASTR * 2));
        ah[q * 2] = h01; ah[q * 2 + 1] = h23;
    };

    // prologue: full build of first tile into buffer 0 (16 rows/thread)
    if (blockIdx.x < nTiles) {
        #pragma unroll
        for (int j = 0; j < 16; j++) {
            const int r = rq + j * 8;
            float4 a, b;
            gatherRow(blockIdx.x * TR + r, a, b);
            uint32_t h01, h23;
            cvt4h(a, b, ms4, rs4, h01, h23);
            stsRow(smraw, r, h01, h23);
        }
    }
    __syncthreads();

    int cur = 0;
    for (int t = blockIdx.x; t < nTiles; t += stride) {
        const int nt = t + stride;
        const bool pf = (nt < nTiles);
        const uint32_t curA = smBase + cur * ABUF;
        char* nxtA = smraw + (cur ^ 1) * ABUF;

        float acc[4][4];
        #pragma unroll
        for (int nb = 0; nb < 4; nb++)
            #pragma unroll
            for (int c = 0; c < 4; c++) acc[nb][c] = 0.0f;

        // fragment double buffers
        uint32_t fA[2][4], fB[2][8];
        #define LDFRAG(buf, kb)                                               \
        {                                                                     \
            ldsm_x4(fA[buf][0], fA[buf][1], fA[buf][2], fA[buf][3],           \
                    curA + aOff + (kb) * 32);                                 \
            const uint32_t bk = BhA + bOff + (kb) * (16 * BSTR * 2);          \
            ldsm_x4_t(fB[buf][0], fB[buf][1], fB[buf][2], fB[buf][3], bk);    \
            ldsm_x4_t(fB[buf][4], fB[buf][5], fB[buf][6], fB[buf][7], bk + 32); \
        }
        #define MMAFRAG(buf)                                                  \
        {                                                                     \
            mma16816h(acc[0], fA[buf][0], fA[buf][1], fA[buf][2], fA[buf][3], \
                      fB[buf][0], fB[buf][1]);                                \
            mma16816h(acc[1], fA[buf][0], fA[buf][1], fA[buf][2], fA[buf][3], \
                      fB[buf][2], fB[buf][3]);                                \
            mma16816h(acc[2], fA[buf][0], fA[buf][1], fA[buf][2], fA[buf][3], \
                      fB[buf][4], fB[buf][5]);                                \
            mma16816h(acc[3], fA[buf][0], fA[buf][1], fA[buf][2], fA[buf][3], \
                      fB[buf][6], fB[buf][7]);                                \
        }

        float4 pa[2], pb[2];
        LDFRAG(0, 0)
        #pragma unroll
        for (int g = 0; g < 8; g++) {
            // gather 2 rows (j = 2g, 2g+1) for next tile
            if (pf) {
                gatherRow(nt * TR + rq + (2 * g) * 8,     pa[0], pb[0]);
                gatherRow(nt * TR + rq + (2 * g + 1) * 8, pa[1], pb[1]);
            }
            LDFRAG(1, 2 * g + 1)
            MMAFRAG(0)
            if (g < 7) LDFRAG(0, 2 * g + 2)
            MMAFRAG(1)
            if (pf) {
                uint32_t h01, h23;
                cvt4h(pa[0], pb[0], ms4, rs4, h01, h23);
                stsRow(nxtA, rq + (2 * g) * 8, h01, h23);
                cvt4h(pa[1], pb[1], ms4, rs4, h01, h23);
                stsRow(nxtA, rq + (2 * g + 1) * 8, h01, h23);
            }
        }
        #undef LDFRAG
        #undef MMAFRAG

        // ---- epilogue: +bias (smem), store Y2 (fp16x2), accumulate stats2 ----
        {
            const int g_  = lane >> 2;
            const int e0 = t * TR + wm * 16 + g_;
            const int e1 = e0 + 8;
            #pragma unroll
            for (int nb = 0; nb < 4; nb++) {
                const int c = wn * 32 + nb * 8 + tg * 2;
                const float bx = b2s[c], by = b2s[c + 1];
                if (e0 < E) {
                    const float ox = acc[nb][0] + bx;
                    const float oy = acc[nb][1] + by;
                    const __half2 h = __floats2half2_rn(ox, oy);
                    g_Y2h[(size_t)e0 * 32 + (c >> 1)] = *(const uint32_t*)&h;
                    sSum[nb * 2 + 0] += ox; sSq[nb * 2 + 0] += ox * ox;
                    sSum[nb * 2 + 1] += oy; sSq[nb * 2 + 1] += oy * oy;
                }
                if (e1 < E) {
                    const float ox = acc[nb][2] + bx;
                    const float oy = acc[nb][3] + by;
                    const __half2 h = __floats2half2_rn(ox, oy);
                    g_Y2h[(size_t)e1 * 32 + (c >> 1)] = *(const uint32_t*)&h;
                    sSum[nb * 2 + 0] += ox; sSq[nb * 2 + 0] += ox * ox;
                    sSum[nb * 2 + 1] += oy; sSq[nb * 2 + 1] += oy * oy;
                }
            }
        }
        __syncthreads();
        cur ^= 1;
    }

    // ---- stats2 reduction: smem scratch, global atomics, fused fin2 ----
    float* sS = (float*)smraw;       // 64 floats
    float* sQ = sS + 64;             // 64 floats
    __syncthreads();
    if (tid < 128) sS[tid] = 0.f;
    __syncthreads();
    #pragma unroll
    for (int nb = 0; nb < 4; nb++) {
        const int c = wn * 32 + nb * 8 + tg * 2;
        atomicAdd(&sS[c],     sSum[nb * 2 + 0]);
        atomicAdd(&sS[c + 1], sSum[nb * 2 + 1]);
        atomicAdd(&sQ[c],     sSq[nb * 2 + 0]);
        atomicAdd(&sQ[c + 1], sSq[nb * 2 + 1]);
    }
    __syncthreads();
    if (tid < C2) {
        atomicAdd(&g_s2[tid],      sS[tid]);
        atomicAdd(&g_s2[C2 + tid], sQ[tid]);
    }

    __shared__ int sLast;
    __threadfence();
    __syncthreads();
    if (tid == 0)
        sLast = (atomicAdd(&g_cnt2, 1) == (int)gridDim.x - 1) ? 1 : 0;
    __syncthreads();
    if (sLast && tid < C2) {
        const float inv = 1.0f / (float)E;
        const float m   = __ldcg(&g_s2[tid]) * inv;
        const float var = __ldcg(&g_s2[C2 + tid]) * inv - m * m;
        g_mr2[tid]      = m;
        g_mr2[C2 + tid] = rsqrtf(var + EPSV);
    }
}

// ================= layer 3: 2 edges/warp, fp16 Y2 reads =================
__global__ __launch_bounds__(256)
void k_out(const float* __restrict__ W3,
           const float* __restrict__ b3,
           float* __restrict__ out,
           int E)
{
    __shared__ float w[C2], m[C2], rs[C2];
    const int tid = threadIdx.x;
    if (tid < C2) {
        w[tid]  = W3[tid];
        m[tid]  = g_mr2[tid];
        rs[tid] = g_mr2[C2 + tid];
    }
    __syncthreads();

    const int lane = tid & 31;
    const int warp = tid >> 5;
    const int sub  = lane >> 4;           // 0/1: which edge in warp
    const int cq   = lane & 15;           // 4 channels each
    const int e = blockIdx.x * 16 + warp * 2 + sub;
    const bool valid = (e < E);

    float p = 0.0f;
    if (valid) {
        const uint2 u = ((const uint2*)(g_Y2h + (size_t)e * 32))[cq];
        const float2 y01 = __half22float2(*(const __half2*)&u.x);
        const float2 y23 = __half22float2(*(const __half2*)&u.y);
        const int c = cq * 4;
        p  = fmaxf(0.f, (y01.x - m[c])     * rs[c])     * w[c];
        p += fmaxf(0.f, (y01.y - m[c + 1]) * rs[c + 1]) * w[c + 1];
        p += fmaxf(0.f, (y23.x - m[c + 2]) * rs[c + 2]) * w[c + 2];
        p += fmaxf(0.f, (y23.y - m[c + 3]) * rs[c + 3]) * w[c + 3];
    }
    #pragma unroll
    for (int o = 8; o > 0; o >>= 1) p += __shfl_xor_sync(0xffffffffu, p, o);
    if (valid && cq == 0) out[e] = p + b3[0];
}

// ================= launch =================
extern "C" void kernel_launch(void* const* d_in, const int* in_sizes, int n_in,
                              void* d_out, int out_size)
{
    const float* emb = (const float*)d_in[0];
    const void*  ei  = d_in[1];
    const float* W1  = (const float*)d_in[2];
    const float* b1  = (const float*)d_in[3];
    const float* W2  = (const float*)d_in[4];
    const float* b2  = (const float*)d_in[5];
    const float* W3  = (const float*)d_in[6];
    const float* b3  = (const float*)d_in[7];
    float* out = (float*)d_out;

    const int N = in_sizes[0] / H;
    const int E = in_sizes[1] / 2;

    int dev = 0;
    cudaGetDevice(&dev);
    int nsm = 148;
    cudaDeviceGetAttribute(&nsm, cudaDevAttrMultiProcessorCount, dev);

    const int smP = (K1DIM * C1 + 32 * H) * (int)sizeof(float);   // 139264
    cudaFuncSetAttribute(k_proj,      cudaFuncAttributeMaxDynamicSharedMemorySize, smP);
    cudaFuncSetAttribute(k_gemm2_mma, cudaFuncAttributeMaxDynamicSharedMemorySize, SMT_G2);

    const int nTiles = (E + TR - 1) / TR;
    int g2 = nsm;
    if (g2 > nTiles) g2 = nTiles;

    k_pre<<<1024, 256>>>((const int*)ei, E);
    k_proj<<<nsm, 256, smP>>>(emb, W1, b1, N);
    k_stats1<<<nsm * 8, 256>>>(E);
    k_gemm2_mma<<<g2, 512, SMT_G2>>>(W2, b2, E);
    k_out<<<(E + 15) / 16, 256>>>(W3, b3, out, E);
}